// round 12
// baseline (speedup 1.0000x reference)
#include <cuda_runtime.h>

#define HH   512
#define WW   512
#define BB   4
#define CINC 55
#define NRr  30
#define NCc  20
#define NCELL 600
#define OUTX 57671680   // 4*55*512*512

// Scratch (device globals; no allocation)
__device__ float g_Stop[NCELL];
__device__ float g_Sbot[NCELL];
__device__ float g_topm[NCELL];
__device__ float g_sig[NCELL];
__device__ float g_wtsum[18];
// Pre-arranged B fragments for mma.m16n8k8.tf32:
// [d][tap][chunk][lane*2 + {0,1}] = tf32(W[n=lane/4][ch=8*chunk+(lane%4)(+4)][tap])
__device__ float g_bfrag[3 * 25 * 7 * 64];

__device__ __forceinline__ unsigned f2tf32(float v) {
    unsigned r;
    asm("cvt.rna.tf32.f32 %0, %1;" : "=r"(r) : "f"(v));
    return r;
}

__device__ __forceinline__ void mma_tf32(float c[4],
                                         unsigned a0, unsigned a1,
                                         unsigned a2, unsigned a3,
                                         unsigned b0, unsigned b1) {
    asm volatile(
        "mma.sync.aligned.m16n8k8.row.col.f32.tf32.tf32.f32 "
        "{%0,%1,%2,%3}, {%4,%5,%6,%7}, {%8,%9}, {%0,%1,%2,%3};"
        : "+f"(c[0]), "+f"(c[1]), "+f"(c[2]), "+f"(c[3])
        : "r"(a0), "r"(a1), "r"(a2), "r"(a3), "r"(b0), "r"(b1));
}

// ---------------------------------------------------------------------------
// Kernel 1: zero cell accumulators; fold top head (36->18 channel-sum);
// build lane-ordered tf32 B-fragments for every (dilation, tap, chunk).
// ---------------------------------------------------------------------------
__global__ __launch_bounds__(256) void prep_kernel(
    const float* __restrict__ w1, const float* __restrict__ w2,
    const float* __restrict__ w3, const float* __restrict__ wt)
{
    int idx = blockIdx.x * 256 + threadIdx.x;
    if (idx < 16800) {                     // 3*25*7*32 lanes
        int lane = idx & 31;
        int t2   = idx >> 5;               // 0..524
        int kc   = t2 % 7;
        int t3   = t2 / 7;
        int kk   = t3 % 25;
        int d    = t3 / 25;
        const float* w = (d == 0) ? w1 : (d == 1 ? w2 : w3);
        int n   = lane >> 2;
        int klo = lane & 3;
        float v0 = 0.f, v1 = 0.f;
        if (n < 6) {
            int ch0 = kc * 8 + klo;
            int ch1 = ch0 + 4;
            if (ch0 < CINC) v0 = w[(n * CINC + ch0) * 25 + kk];
            if (ch1 < CINC) v1 = w[(n * CINC + ch1) * 25 + kk];
        }
        int base = ((d * 25 + kk) * 7 + kc) * 64 + lane * 2;
        g_bfrag[base]     = __uint_as_float(f2tf32(v0));
        g_bfrag[base + 1] = __uint_as_float(f2tf32(v1));
    } else if (idx < 16800 + NCELL) {
        int t = idx - 16800;
        g_Stop[t] = 0.f;
        g_Sbot[t] = 0.f;
    } else if (idx < 16800 + NCELL + 18) {
        int t = idx - 16800 - NCELL;
        float s = 0.f;
        #pragma unroll 4
        for (int c = 0; c < 36; c++) s += wt[c * 18 + t];
        g_wtsum[t] = s;
    }
}

// ---------------------------------------------------------------------------
// Kernel 2: TF32 tensor-core dilated conv (shift-GEMM). Per block: one
// (batch, dilation), 32x32 pixel tile, K-loop over 7 chunks of 8 channels
// staged as tf32 planes in SMEM (plane stride 1944 words, conflict-free
// quad access). Inner loop over 25 taps: B-frag via one __ldg float2,
// 8 m-tiles (16 pixels each) per warp -> mma.m16n8k8.
// Staging: uniform interior fast path (float2, no guards); 3 blocks/SM.
// ---------------------------------------------------------------------------
#define PLSTRIDE 1944

template <int D>
__device__ __forceinline__ void conv_body(
    const float* __restrict__ x,
    const float* __restrict__ bias6,
    float* __restrict__ out,
    unsigned* sm, int b, int gx0, int gy0)
{
    constexpr int PAD = 2 * D;
    constexpr int SW  = 32 + 4 * D;
    constexpr int SH  = 32 + 4 * D;
    constexpr int SW2 = SW / 2;
    constexpr int OCB = 36 + 6 * (D - 1);

    const int tid  = threadIdx.x;
    const int lane = tid & 31;
    const int w    = tid >> 5;     // warp 0..7 -> rows w*4..w*4+3

    const bool interior = (gx0 != 0) && (gx0 != WW - 32) &&
                          (gy0 != 0) && (gy0 != HH - 32);

    const int thrbase = (lane & 3) * PLSTRIDE + (lane >> 2);
    int mtoff[8];
    #pragma unroll
    for (int mt = 0; mt < 8; mt++)
        mtoff[mt] = (w * 4 + (mt >> 1)) * SW + (mt & 1) * 16 + thrbase;

    float acc[8][4];
    #pragma unroll
    for (int mt = 0; mt < 8; mt++)
        #pragma unroll
        for (int j = 0; j < 4; j++) acc[mt][j] = 0.f;

    // base pointer to (gy0-PAD, gx0-PAD) of channel 0 of this batch
    const float* xb = x + (((size_t)b * CINC) << 18)
                        + ((gy0 - PAD) << 9) + (gx0 - PAD);

    for (int kc = 0; kc < 7; kc++) {
        if (interior) {
            // fast path: float2 loads/stores, no per-element guards
            #pragma unroll 1
            for (int i = tid; i < 8 * SH * SW2; i += 256) {
                int p   = i / (SH * SW2);
                int rem = i - p * (SH * SW2);
                int r   = rem / SW2;
                int c2  = rem - r * SW2;
                int ch  = kc * 8 + p;
                float2 v = make_float2(0.f, 0.f);
                if (ch < CINC)
                    v = *(const float2*)(xb + ((size_t)ch << 18) + (r << 9) + 2 * c2);
                unsigned* dst = sm + p * PLSTRIDE + r * SW + 2 * c2;
                dst[0] = f2tf32(v.x);
                dst[1] = f2tf32(v.y);
            }
        } else {
            #pragma unroll 1
            for (int i = tid; i < 8 * SH * SW; i += 256) {
                int p   = i / (SH * SW);
                int rem = i - p * (SH * SW);
                int r   = rem / SW;
                int cc  = rem - r * SW;
                int ch  = kc * 8 + p;
                int gy  = gy0 - PAD + r;
                int gx  = gx0 - PAD + cc;
                float v = 0.f;
                if (ch < CINC && (unsigned)gy < 512u && (unsigned)gx < 512u)
                    v = x[(((size_t)(b * CINC + ch)) << 18) + (gy << 9) + gx];
                sm[p * PLSTRIDE + r * SW + cc] = f2tf32(v);
            }
        }
        __syncthreads();

        #pragma unroll 5
        for (int kk = 0; kk < 25; kk++) {
            float2 bf = *(const float2*)&g_bfrag[
                (((D - 1) * 25 + kk) * 7 + kc) * 64 + lane * 2];
            unsigned b0 = __float_as_uint(bf.x);
            unsigned b1 = __float_as_uint(bf.y);
            const int tapoff = (kk / 5) * D * SW + (kk % 5) * D;
            #pragma unroll
            for (int mt = 0; mt < 8; mt++) {
                const unsigned* ap = sm + mtoff[mt] + tapoff;
                unsigned a0 = ap[0];
                unsigned a1 = ap[8];
                unsigned a2 = ap[4 * PLSTRIDE];
                unsigned a3 = ap[4 * PLSTRIDE + 8];
                mma_tf32(acc[mt], a0, a1, a2, a3, b0, b1);
            }
        }
        __syncthreads();
    }

    // epilogue: bias + relu, scalar feat stores (C-frag layout)
    const int n0 = (lane & 3) * 2;
    if (n0 < 6) {
        float bi0 = __ldg(&bias6[n0]);
        float bi1 = __ldg(&bias6[n0 + 1]);
        const size_t ch0base = ((size_t)(b * CINC + OCB + n0))     << 18;
        const size_t ch1base = ((size_t)(b * CINC + OCB + n0 + 1)) << 18;
        #pragma unroll
        for (int mt = 0; mt < 8; mt++) {
            int y  = gy0 + w * 4 + (mt >> 1);
            int gx = gx0 + (mt & 1) * 16 + (lane >> 2);
            unsigned pix = ((unsigned)y << 9) + (unsigned)gx;
            out[ch0base + pix]     = fmaxf(acc[mt][0] + bi0, 0.f);
            out[ch1base + pix]     = fmaxf(acc[mt][1] + bi1, 0.f);
            out[ch0base + pix + 8] = fmaxf(acc[mt][2] + bi0, 0.f);
            out[ch1base + pix + 8] = fmaxf(acc[mt][3] + bi1, 0.f);
        }
    }
}

extern __shared__ unsigned smu[];

__global__ __launch_bounds__(256, 3) void conv_kernel(
    const float* __restrict__ x,
    const float* __restrict__ b1, const float* __restrict__ b2,
    const float* __restrict__ b3,
    float* __restrict__ out)
{
    const int z   = blockIdx.z;
    const int b   = z / 3;
    const int d   = z - b * 3;
    const int gx0 = blockIdx.x * 32;
    const int gy0 = blockIdx.y * 32;
    if (d == 0)      conv_body<1>(x, b1, out, smu, b, gx0, gy0);
    else if (d == 1) conv_body<2>(x, b2, out, smu, b, gx0, gy0);
    else             conv_body<3>(x, b3, out, smu, b, gx0, gy0);
}

// ---------------------------------------------------------------------------
// Kernel 3: head reduction — read feat (channels 36..53) back (L2-hot),
// form per-pixel channel-sum head values, accumulate into per-cell sums.
// ---------------------------------------------------------------------------
__global__ __launch_bounds__(256) void reduce_kernel(
    const int* __restrict__ row_seg, const int* __restrict__ col_seg,
    const float* __restrict__ wbv, const float* __restrict__ out)
{
    __shared__ float cT[NCELL], cB[NCELL];
    __shared__ float swt[18], swb[18];
    const int tid = threadIdx.x;
    for (int t = tid; t < NCELL; t += 256) { cT[t] = 0.f; cB[t] = 0.f; }
    if (tid < 18) { swt[tid] = g_wtsum[tid]; swb[tid] = __ldg(&wbv[tid]); }
    __syncthreads();

    unsigned i  = blockIdx.x * 256u + tid;
    unsigned x4 = (i & 127u) << 2;
    unsigned y  = (i >> 7) & 511u;
    unsigned b  = i >> 16;
    float st0 = 0.f, st1 = 0.f, st2 = 0.f, st3 = 0.f;
    float sb0 = 0.f, sb1 = 0.f, sb2 = 0.f, sb3 = 0.f;
    const size_t base = ((size_t)(b * CINC + 36) << 18) + (y << 9) + x4;
    #pragma unroll
    for (int j = 0; j < 18; j++) {
        float4 f = *(const float4*)&out[base + ((size_t)j << 18)];
        float wj = swt[j], vj = swb[j];
        st0 = fmaf(wj, f.x, st0); st1 = fmaf(wj, f.y, st1);
        st2 = fmaf(wj, f.z, st2); st3 = fmaf(wj, f.w, st3);
        sb0 = fmaf(vj, f.x, sb0); sb1 = fmaf(vj, f.y, sb1);
        sb2 = fmaf(vj, f.z, sb2); sb3 = fmaf(vj, f.w, sb3);
    }
    const int rb = row_seg[y] * NCc;
    const int c0 = col_seg[x4],     c1 = col_seg[x4 + 1];
    const int c2 = col_seg[x4 + 2], c3 = col_seg[x4 + 3];
    atomicAdd(&cT[rb + c0], st0); atomicAdd(&cT[rb + c1], st1);
    atomicAdd(&cT[rb + c2], st2); atomicAdd(&cT[rb + c3], st3);
    atomicAdd(&cB[rb + c0], sb0); atomicAdd(&cB[rb + c1], sb1);
    atomicAdd(&cB[rb + c2], sb2); atomicAdd(&cB[rb + c3], sb3);
    __syncthreads();
    for (int t = tid; t < NCELL; t += 256) {
        float v0 = cT[t], v1 = cB[t];
        if (v0 != 0.f) atomicAdd(&g_Stop[t], v0);
        if (v1 != 0.f) atomicAdd(&g_Sbot[t], v1);
    }
}

// ---------------------------------------------------------------------------
// Kernel 4: finalize means (adding head biases) -> top_m, sigmoid(bot_m);
// write pools output.
// ---------------------------------------------------------------------------
__global__ __launch_bounds__(640) void finalize_kernel(
    const int* __restrict__ row_seg, const int* __restrict__ col_seg,
    const float* __restrict__ bt, const float* __restrict__ bb,
    float* __restrict__ out)
{
    __shared__ int rc[NRr];
    __shared__ int cc[NCc];
    int t = threadIdx.x;
    if (t < NRr) rc[t] = 0;
    if (t < NCc) cc[t] = 0;
    __syncthreads();
    if (t < 512) {
        atomicAdd(&rc[row_seg[t]], 1);
        atomicAdd(&cc[col_seg[t]], 1);
    }
    __syncthreads();
    if (t < NCELL) {
        float btsum = 0.f;
        for (int c = 0; c < 36; c++) btsum += bt[c];
        float bb0 = bb[0];
        int r = t / NCc, c = t - r * NCc;
        float pix = (float)(rc[r] * cc[c]);
        float tm = (g_Stop[t] + (float)BB * pix * btsum) / (pix * (float)(BB * 36));
        float bm = (g_Sbot[t] + (float)BB * pix * bb0) / (pix * (float)BB);
        g_topm[t] = tm;
        float sg = 1.f / (1.f + expf(-bm));
        g_sig[t] = sg;
        #pragma unroll
        for (int b = 0; b < BB; b++)
            out[OUTX + b * NCELL + t] = sg;
    }
}

// ---------------------------------------------------------------------------
// Kernel 5: broadcast fill of channels 0..35 (top_m) and 54 (sigmoid(bot_m)).
// ---------------------------------------------------------------------------
__global__ __launch_bounds__(256) void bcast_kernel(
    const int* __restrict__ row_seg, const int* __restrict__ col_seg,
    float* __restrict__ out)
{
    unsigned i  = blockIdx.x * 256u + threadIdx.x;   // over B*H*W/4
    unsigned x4 = (i & 127u) << 2;
    unsigned y  = (i >> 7) & 511u;
    unsigned b  = i >> 16;
    int rb = __ldg(&row_seg[y]) * NCc;
    int c0 = __ldg(&col_seg[x4]);
    int c1 = __ldg(&col_seg[x4 + 1]);
    int c2 = __ldg(&col_seg[x4 + 2]);
    int c3 = __ldg(&col_seg[x4 + 3]);
    float4 tv = make_float4(g_topm[rb + c0], g_topm[rb + c1],
                            g_topm[rb + c2], g_topm[rb + c3]);
    float4 sv = make_float4(g_sig[rb + c0], g_sig[rb + c1],
                            g_sig[rb + c2], g_sig[rb + c3]);
    unsigned base = ((b * (unsigned)CINC) << 18) + (y << 9) + x4;
    #pragma unroll
    for (int ch = 0; ch < 36; ch++)
        *(float4*)&out[base + ((unsigned)ch << 18)] = tv;
    *(float4*)&out[base + (54u << 18)] = sv;
}

// ---------------------------------------------------------------------------
extern "C" void kernel_launch(void* const* d_in, const int* in_sizes, int n_in,
                              void* d_out, int out_size) {
    const float* x       = (const float*)d_in[0];
    const int*   row_seg = (const int*)d_in[1];
    const int*   col_seg = (const int*)d_in[2];
    const float* w1 = (const float*)d_in[3];
    const float* b1 = (const float*)d_in[4];
    const float* w2 = (const float*)d_in[5];
    const float* b2 = (const float*)d_in[6];
    const float* w3 = (const float*)d_in[7];
    const float* b3 = (const float*)d_in[8];
    const float* wt = (const float*)d_in[9];
    const float* bt = (const float*)d_in[10];
    const float* wb = (const float*)d_in[11];
    const float* bb = (const float*)d_in[12];
    float* out = (float*)d_out;

    prep_kernel<<<69, 256>>>(w1, w2, w3, wt);

    const int smbytes = 8 * PLSTRIDE * 4;   // 62208
    cudaFuncSetAttribute(conv_kernel,
                         cudaFuncAttributeMaxDynamicSharedMemorySize, smbytes);
    dim3 grid(WW / 32, HH / 32, BB * 3);    // 16 x 16 x 12
    conv_kernel<<<grid, 256, smbytes>>>(x, b1, b2, b3, out);

    reduce_kernel<<<(BB * HH * WW / 4) / 256, 256>>>(row_seg, col_seg, wb, out);

    finalize_kernel<<<1, 640>>>(row_seg, col_seg, bt, bb, out);

    bcast_kernel<<<(BB * HH * WW / 4) / 256, 256>>>(row_seg, col_seg, out);
}

// round 13
// speedup vs baseline: 1.1255x; 1.1255x over previous
#include <cuda_runtime.h>

#define HH   512
#define WW   512
#define BB   4
#define CINC 55
#define NRr  30
#define NCc  20
#define NCELL 600
#define OUTX 57671680   // 4*55*512*512

// Scratch (device globals; no allocation)
__device__ float g_Stop[NCELL];
__device__ float g_Sbot[NCELL];
__device__ float g_topm[NCELL];
__device__ float g_sig[NCELL];
__device__ float g_wtsum[18];
// B fragments for mma.m16n8k4.tf32: [d][tap][kc14][lane] =
//   tf32(W[n=lane/4][ch=4*kc+(lane%4)][tap]) * (1+2^-11)  (truncation comp.)
__device__ float g_bfrag[3 * 25 * 14 * 32];

__device__ __forceinline__ unsigned f2tf32(float v) {
    unsigned r;
    asm("cvt.rna.tf32.f32 %0, %1;" : "=r"(r) : "f"(v));
    return r;
}

__device__ __forceinline__ void mma_k4(float c[4], unsigned a0, unsigned a1,
                                       unsigned b0) {
    asm volatile(
        "mma.sync.aligned.m16n8k4.row.col.f32.tf32.tf32.f32 "
        "{%0,%1,%2,%3}, {%4,%5}, {%6}, {%0,%1,%2,%3};"
        : "+f"(c[0]), "+f"(c[1]), "+f"(c[2]), "+f"(c[3])
        : "r"(a0), "r"(a1), "r"(b0));
}

__device__ __forceinline__ void cp4(unsigned dst, const float* src) {
    asm volatile("cp.async.ca.shared.global [%0], [%1], 4;"
                 :: "r"(dst), "l"(src));
}
#define CP_COMMIT() asm volatile("cp.async.commit_group;")
#define CP_WAIT1()  asm volatile("cp.async.wait_group 1;")
#define CP_WAIT0()  asm volatile("cp.async.wait_group 0;")

// ---------------------------------------------------------------------------
// Kernel 1: zero cell accumulators; fold top head (36->18 channel-sum);
// build lane-ordered tf32 B-fragments (14 K=4 chunks), with (1+2^-11)
// compensation for A-operand tf32 truncation.
// ---------------------------------------------------------------------------
__global__ __launch_bounds__(256) void prep_kernel(
    const float* __restrict__ w1, const float* __restrict__ w2,
    const float* __restrict__ w3, const float* __restrict__ wt)
{
    int idx = blockIdx.x * 256 + threadIdx.x;
    if (idx < 33600) {                       // 3*25*14*32
        int lane = idx & 31;
        int t2   = idx >> 5;                 // 0..1049
        int kc   = t2 % 14;
        int t3   = t2 / 14;
        int kk   = t3 % 25;
        int d    = t3 / 25;
        const float* w = (d == 0) ? w1 : (d == 1 ? w2 : w3);
        int n  = lane >> 2;
        int ch = kc * 4 + (lane & 3);
        float v = 0.f;
        if (n < 6 && ch < CINC)
            v = w[(n * CINC + ch) * 25 + kk] * 1.00048828125f;
        g_bfrag[idx] = __uint_as_float(f2tf32(v));
    } else if (idx < 33600 + NCELL) {
        int t = idx - 33600;
        g_Stop[t] = 0.f;
        g_Sbot[t] = 0.f;
    } else if (idx < 33600 + NCELL + 18) {
        int t = idx - 33600 - NCELL;
        float s = 0.f;
        #pragma unroll 4
        for (int c = 0; c < 36; c++) s += wt[c * 18 + t];
        g_wtsum[t] = s;
    }
}

// ---------------------------------------------------------------------------
// Kernel 2: TF32 shift-GEMM dilated conv, cp.async double-buffered.
// Per block: one (batch, dilation), 32x32 pixel tile. 14 chunks of 4
// channel planes (fp32 raw; HW truncates to tf32 at mma). Plane stride 1944
// words -> conflict-free A-fragment LDS. Inner: 25 taps x 8 m-tiles,
// mma.m16n8k4. Both buffers pre-zeroed once (spatial halo mask is
// chunk-invariant); channel-pad plane STS-zeroed.
// ---------------------------------------------------------------------------
#define PLSTRIDE 1944
#define BUFOFF   (4 * PLSTRIDE)

extern __shared__ unsigned smu[];

template <int D>
__device__ __forceinline__ void conv_body(
    const float* __restrict__ x,
    const float* __restrict__ bias6,
    float* __restrict__ out, int b, int gx0, int gy0)
{
    constexpr int PAD = 2 * D;
    constexpr int SW  = 32 + 4 * D;
    constexpr int SH  = 32 + 4 * D;
    constexpr int OCB = 36 + 6 * (D - 1);

    const int tid  = threadIdx.x;
    const int lane = tid & 31;
    const int w    = tid >> 5;

    unsigned smb;
    asm("{.reg .u64 t; cvta.to.shared.u64 t, %1; cvt.u32.u64 %0, t;}"
        : "=r"(smb) : "l"(smu));

    // pre-zero both buffers (halo cells stay zero for all chunks)
    for (int i = tid; i < 2 * BUFOFF; i += 256) smu[i] = 0u;
    __syncthreads();

    const float* xb = x + (((size_t)b * CINC) << 18)
                        + ((gy0 - PAD) << 9) + (gx0 - PAD);

    // ---- staging (warp-structured; cp.async per in-bounds element) ----
    auto stage = [&](int kc) {
        const int bo = (kc & 1) * BUFOFF;
        #pragma unroll
        for (int p = 0; p < 4; p++) {
            const int ch = kc * 4 + p;
            if (ch < CINC) {
                const float* src = xb + ((size_t)ch << 18);
                #pragma unroll
                for (int rr = 0; rr < (SH + 7) / 8; rr++) {
                    const int row = w + rr * 8;
                    if (row < SH) {
                        const int gy = gy0 - PAD + row;
                        const bool rok = (unsigned)gy < 512u;
                        #pragma unroll
                        for (int ci = 0; ci < (SW + 31) / 32; ci++) {
                            const int cc = lane + ci * 32;
                            if (cc < SW) {
                                const int gx = gx0 - PAD + cc;
                                if (rok && (unsigned)gx < 512u)
                                    cp4(smb + 4u * (bo + p * PLSTRIDE + row * SW + cc),
                                        src + (row << 9) + cc);
                            }
                        }
                    }
                }
            } else {
                // channel padding (chunk 13): explicit zeros (buffer reused)
                for (int i = tid; i < SH * SW; i += 256)
                    smu[bo + p * PLSTRIDE + i] = 0u;
            }
        }
    };

    const int thrbase = (lane & 3) * PLSTRIDE + (lane >> 2);
    int mtoff[8];
    #pragma unroll
    for (int mt = 0; mt < 8; mt++)
        mtoff[mt] = (w * 4 + (mt >> 1)) * SW + (mt & 1) * 16 + thrbase;

    float acc[8][4];
    #pragma unroll
    for (int mt = 0; mt < 8; mt++)
        #pragma unroll
        for (int j = 0; j < 4; j++) acc[mt][j] = 0.f;

    stage(0);
    CP_COMMIT();

    for (int kc = 0; kc < 14; kc++) {
        if (kc < 13) {
            stage(kc + 1);
            CP_COMMIT();
            CP_WAIT1();
        } else {
            CP_WAIT0();
        }
        __syncthreads();

        const unsigned* sb = smu + (kc & 1) * BUFOFF;
        const float* bf = g_bfrag + ((D - 1) * 25 * 14 + kc) * 32 + lane;
        #pragma unroll 5
        for (int kk = 0; kk < 25; kk++) {
            unsigned b0 = __float_as_uint(__ldg(bf + kk * 14 * 32));
            const int tapoff = (kk / 5) * D * SW + (kk % 5) * D;
            #pragma unroll
            for (int mt = 0; mt < 8; mt++) {
                const unsigned* ap = sb + mtoff[mt] + tapoff;
                mma_k4(acc[mt], ap[0], ap[8], b0);
            }
        }
        __syncthreads();
    }

    // epilogue: bias + relu, scalar feat stores (C-frag layout)
    const int n0 = (lane & 3) * 2;
    if (n0 < 6) {
        float bi0 = __ldg(&bias6[n0]);
        float bi1 = __ldg(&bias6[n0 + 1]);
        const size_t ch0base = ((size_t)(b * CINC + OCB + n0))     << 18;
        const size_t ch1base = ((size_t)(b * CINC + OCB + n0 + 1)) << 18;
        #pragma unroll
        for (int mt = 0; mt < 8; mt++) {
            int y  = gy0 + w * 4 + (mt >> 1);
            int gx = gx0 + (mt & 1) * 16 + (lane >> 2);
            unsigned pix = ((unsigned)y << 9) + (unsigned)gx;
            out[ch0base + pix]     = fmaxf(acc[mt][0] + bi0, 0.f);
            out[ch1base + pix]     = fmaxf(acc[mt][1] + bi1, 0.f);
            out[ch0base + pix + 8] = fmaxf(acc[mt][2] + bi0, 0.f);
            out[ch1base + pix + 8] = fmaxf(acc[mt][3] + bi1, 0.f);
        }
    }
}

__global__ __launch_bounds__(256, 2) void conv_kernel(
    const float* __restrict__ x,
    const float* __restrict__ b1, const float* __restrict__ b2,
    const float* __restrict__ b3,
    float* __restrict__ out)
{
    const int z   = blockIdx.z;
    const int b   = z / 3;
    const int d   = z - b * 3;
    const int gx0 = blockIdx.x * 32;
    const int gy0 = blockIdx.y * 32;
    if (d == 0)      conv_body<1>(x, b1, out, b, gx0, gy0);
    else if (d == 1) conv_body<2>(x, b2, out, b, gx0, gy0);
    else             conv_body<3>(x, b3, out, b, gx0, gy0);
}

// ---------------------------------------------------------------------------
// Kernel 3: head reduction — read feat (channels 36..53) back (L2-hot),
// form per-pixel channel-sum head values, accumulate into per-cell sums.
// ---------------------------------------------------------------------------
__global__ __launch_bounds__(256) void reduce_kernel(
    const int* __restrict__ row_seg, const int* __restrict__ col_seg,
    const float* __restrict__ wbv, const float* __restrict__ out)
{
    __shared__ float cT[NCELL], cB[NCELL];
    __shared__ float swt[18], swb[18];
    const int tid = threadIdx.x;
    for (int t = tid; t < NCELL; t += 256) { cT[t] = 0.f; cB[t] = 0.f; }
    if (tid < 18) { swt[tid] = g_wtsum[tid]; swb[tid] = __ldg(&wbv[tid]); }
    __syncthreads();

    unsigned i  = blockIdx.x * 256u + tid;
    unsigned x4 = (i & 127u) << 2;
    unsigned y  = (i >> 7) & 511u;
    unsigned b  = i >> 16;
    float st0 = 0.f, st1 = 0.f, st2 = 0.f, st3 = 0.f;
    float sb0 = 0.f, sb1 = 0.f, sb2 = 0.f, sb3 = 0.f;
    const size_t base = ((size_t)(b * CINC + 36) << 18) + (y << 9) + x4;
    #pragma unroll
    for (int j = 0; j < 18; j++) {
        float4 f = *(const float4*)&out[base + ((size_t)j << 18)];
        float wj = swt[j], vj = swb[j];
        st0 = fmaf(wj, f.x, st0); st1 = fmaf(wj, f.y, st1);
        st2 = fmaf(wj, f.z, st2); st3 = fmaf(wj, f.w, st3);
        sb0 = fmaf(vj, f.x, sb0); sb1 = fmaf(vj, f.y, sb1);
        sb2 = fmaf(vj, f.z, sb2); sb3 = fmaf(vj, f.w, sb3);
    }
    const int rb = row_seg[y] * NCc;
    const int c0 = col_seg[x4],     c1 = col_seg[x4 + 1];
    const int c2 = col_seg[x4 + 2], c3 = col_seg[x4 + 3];
    atomicAdd(&cT[rb + c0], st0); atomicAdd(&cT[rb + c1], st1);
    atomicAdd(&cT[rb + c2], st2); atomicAdd(&cT[rb + c3], st3);
    atomicAdd(&cB[rb + c0], sb0); atomicAdd(&cB[rb + c1], sb1);
    atomicAdd(&cB[rb + c2], sb2); atomicAdd(&cB[rb + c3], sb3);
    __syncthreads();
    for (int t = tid; t < NCELL; t += 256) {
        float v0 = cT[t], v1 = cB[t];
        if (v0 != 0.f) atomicAdd(&g_Stop[t], v0);
        if (v1 != 0.f) atomicAdd(&g_Sbot[t], v1);
    }
}

// ---------------------------------------------------------------------------
// Kernel 4: finalize means (adding head biases) -> top_m, sigmoid(bot_m);
// write pools output.
// ---------------------------------------------------------------------------
__global__ __launch_bounds__(640) void finalize_kernel(
    const int* __restrict__ row_seg, const int* __restrict__ col_seg,
    const float* __restrict__ bt, const float* __restrict__ bb,
    float* __restrict__ out)
{
    __shared__ int rc[NRr];
    __shared__ int cc[NCc];
    int t = threadIdx.x;
    if (t < NRr) rc[t] = 0;
    if (t < NCc) cc[t] = 0;
    __syncthreads();
    if (t < 512) {
        atomicAdd(&rc[row_seg[t]], 1);
        atomicAdd(&cc[col_seg[t]], 1);
    }
    __syncthreads();
    if (t < NCELL) {
        float btsum = 0.f;
        for (int c = 0; c < 36; c++) btsum += bt[c];
        float bb0 = bb[0];
        int r = t / NCc, c = t - r * NCc;
        float pix = (float)(rc[r] * cc[c]);
        float tm = (g_Stop[t] + (float)BB * pix * btsum) / (pix * (float)(BB * 36));
        float bm = (g_Sbot[t] + (float)BB * pix * bb0) / (pix * (float)BB);
        g_topm[t] = tm;
        float sg = 1.f / (1.f + expf(-bm));
        g_sig[t] = sg;
        #pragma unroll
        for (int b = 0; b < BB; b++)
            out[OUTX + b * NCELL + t] = sg;
    }
}

// ---------------------------------------------------------------------------
// Kernel 5: broadcast fill of channels 0..35 (top_m) and 54 (sigmoid(bot_m)).
// ---------------------------------------------------------------------------
__global__ __launch_bounds__(256) void bcast_kernel(
    const int* __restrict__ row_seg, const int* __restrict__ col_seg,
    float* __restrict__ out)
{
    unsigned i  = blockIdx.x * 256u + threadIdx.x;   // over B*H*W/4
    unsigned x4 = (i & 127u) << 2;
    unsigned y  = (i >> 7) & 511u;
    unsigned b  = i >> 16;
    int rb = __ldg(&row_seg[y]) * NCc;
    int c0 = __ldg(&col_seg[x4]);
    int c1 = __ldg(&col_seg[x4 + 1]);
    int c2 = __ldg(&col_seg[x4 + 2]);
    int c3 = __ldg(&col_seg[x4 + 3]);
    float4 tv = make_float4(g_topm[rb + c0], g_topm[rb + c1],
                            g_topm[rb + c2], g_topm[rb + c3]);
    float4 sv = make_float4(g_sig[rb + c0], g_sig[rb + c1],
                            g_sig[rb + c2], g_sig[rb + c3]);
    unsigned base = ((b * (unsigned)CINC) << 18) + (y << 9) + x4;
    #pragma unroll
    for (int ch = 0; ch < 36; ch++)
        *(float4*)&out[base + ((unsigned)ch << 18)] = tv;
    *(float4*)&out[base + (54u << 18)] = sv;
}

// ---------------------------------------------------------------------------
extern "C" void kernel_launch(void* const* d_in, const int* in_sizes, int n_in,
                              void* d_out, int out_size) {
    const float* x       = (const float*)d_in[0];
    const int*   row_seg = (const int*)d_in[1];
    const int*   col_seg = (const int*)d_in[2];
    const float* w1 = (const float*)d_in[3];
    const float* b1 = (const float*)d_in[4];
    const float* w2 = (const float*)d_in[5];
    const float* b2 = (const float*)d_in[6];
    const float* w3 = (const float*)d_in[7];
    const float* b3 = (const float*)d_in[8];
    const float* wt = (const float*)d_in[9];
    const float* bt = (const float*)d_in[10];
    const float* wb = (const float*)d_in[11];
    const float* bb = (const float*)d_in[12];
    float* out = (float*)d_out;

    prep_kernel<<<134, 256>>>(w1, w2, w3, wt);

    const int smbytes = 2 * BUFOFF * 4;     // 62208
    cudaFuncSetAttribute(conv_kernel,
                         cudaFuncAttributeMaxDynamicSharedMemorySize, smbytes);
    dim3 grid(WW / 32, HH / 32, BB * 3);    // 16 x 16 x 12
    conv_kernel<<<grid, 256, smbytes>>>(x, b1, b2, b3, out);

    reduce_kernel<<<(BB * HH * WW / 4) / 256, 256>>>(row_seg, col_seg, wb, out);

    finalize_kernel<<<1, 640>>>(row_seg, col_seg, bt, bb, out);

    bcast_kernel<<<(BB * HH * WW / 4) / 256, 256>>>(row_seg, col_seg, out);
}